// round 14
// baseline (speedup 1.0000x reference)
#include <cuda_runtime.h>
#include <cuda_bf16.h>
#include <cstdint>

// ----------------------------------------------------------------------------
// Constants
// ----------------------------------------------------------------------------
#define NF       196
#define EPB      64
#define NTHREADS 64
#define S4       25          // float4 stride per smem row (400B: conflict-free f4 access)
#define A_F4     24          // phase A: cols [0,96)   -> f4 0..23
#define B_F4     25          // phase B: cols [96,196) -> f4 24..48
#define SMEM_BYTES (2 * EPB * S4 * 16)
#define MAXBLOCKS 608        // 4 CTAs/SM x 152 SMs (GB300)

// pairs (offset,size): ss 0,9  sp 9,18  sd 27,15  ps 42,18  pp 60,36
//                      pd 96,30  ds 126,15  dp 141,30  dd 171,25
// cg offsets: ss0 sp1 sd10 ps35 pp44 pd125 ds350 dp375 dd600

// ----------------------------------------------------------------------------
// Compile-time CG computation: constexpr float64 mirror of the numpy reference.
// ----------------------------------------------------------------------------
struct CD { double re, im; };
constexpr CD cadd(CD a, CD b) { return {a.re + b.re, a.im + b.im}; }
constexpr CD cmulc(CD a, CD b) { return {a.re * b.re - a.im * b.im, a.re * b.im + a.im * b.re}; }
constexpr CD cscale(CD a, double s) { return {a.re * s, a.im * s}; }
constexpr CD cconj(CD a) { return {a.re, -a.im}; }
constexpr bool ciszero(CD a) { return a.re == 0.0 && a.im == 0.0; }

constexpr double cfact(int n) { double r = 1.0; for (int i = 2; i <= n; i++) r *= i; return r; }

constexpr double csqrt_(double x) {
    if (x <= 0.0) return 0.0;
    double y = x > 1.0 ? x : 1.0;
    for (int i = 0; i < 80; i++) {
        double ny = 0.5 * (y + x / y);
        if (ny == y) break;
        y = ny;
    }
    return y;
}

constexpr double su2_cg_c(int j1, int j2, int j3, int m1, int m2, int m3) {
    if (m3 != m1 + m2) return 0.0;
    int vmin = -j1 + j2 + m3;
    if (-j1 + m1 > vmin) vmin = -j1 + m1;
    if (0 > vmin) vmin = 0;
    int vmax = j2 + j3 + m1;
    if (j3 - j1 + j2 < vmax) vmax = j3 - j1 + j2;
    if (j3 + m3 < vmax) vmax = j3 + m3;
    double C = csqrt_((2.0 * j3 + 1.0) * cfact(j3 + j1 - j2) * cfact(j3 - j1 + j2)
                      * cfact(j1 + j2 - j3) * cfact(j3 + m3) * cfact(j3 - m3)
                      / (cfact(j1 + j2 + j3 + 1) * cfact(j1 - m1) * cfact(j1 + m1)
                         * cfact(j2 - m2) * cfact(j2 + m2)));
    double S = 0.0;
    for (int v = vmin; v <= vmax; v++) {
        double sg = ((v + j2 + m2) & 1) ? -1.0 : 1.0;
        S += sg * cfact(j2 + j3 + m1 - v) * cfact(j1 - m1 + v)
             / (cfact(v) * cfact(j3 - j1 + j2 - v) * cfact(j3 + m3 - v)
                * cfact(v + j1 - j2 - m3));
    }
    return C * S;
}

struct QM { CD q[81]; };

constexpr QM change_basis_c(int l) {
    QM Q{};
    int L = 2 * l + 1;
    for (int i = 0; i < L * L; i++) Q.q[i] = CD{0, 0};
    double is2 = 1.0 / csqrt_(2.0);
    for (int m = -l; m < 0; m++) {
        Q.q[(l + m) * L + (l - m)] = CD{is2, 0};
        Q.q[(l + m) * L + (l + m)] = CD{0, -is2};
    }
    Q.q[l * L + l] = CD{1, 0};
    for (int m = 1; m <= l; m++) {
        double sg = (m & 1) ? -1.0 : 1.0;
        Q.q[(l + m) * L + (l + m)] = CD{sg * is2, 0};
        Q.q[(l + m) * L + (l - m)] = CD{0, sg * is2};
    }
    CD ph{1, 0};
    for (int k = 0; k < l; k++) ph = cmulc(ph, CD{0, -1});   // (-i)^l
    for (int i = 0; i < L * L; i++) Q.q[i] = cmulc(Q.q[i], ph);
    return Q;
}

struct W3 { double w[225]; };

constexpr W3 wigner3j_c(int l1, int l2, int l3) {
    int L1 = 2 * l1 + 1, L2 = 2 * l2 + 1, L3 = 2 * l3 + 1;
    QM Q1 = change_basis_c(l1), Q2 = change_basis_c(l2), Q3 = change_basis_c(l3);
    CD acc[225]{};
    for (int t = 0; t < 225; t++) acc[t] = CD{0, 0};
    for (int i = 0; i < L1; i++)
        for (int k = 0; k < L2; k++)
            for (int n = 0; n < L3; n++) {
                double c = su2_cg_c(l1, l2, l3, i - l1, k - l2, n - l3);
                if (c == 0.0) continue;
                for (int j = 0; j < L1; j++) {
                    CD q1 = Q1.q[i * L1 + j];
                    if (ciszero(q1)) continue;
                    for (int l = 0; l < L2; l++) {
                        CD q2 = Q2.q[k * L2 + l];
                        if (ciszero(q2)) continue;
                        CD q12 = cmulc(q1, q2);
                        for (int m = 0; m < L3; m++) {
                            CD q3 = Q3.q[n * L3 + m];
                            if (ciszero(q3)) continue;
                            CD t = cmulc(q12, cconj(q3));
                            int o = (j * L2 + l) * L3 + m;
                            acc[o] = cadd(acc[o], cscale(t, c));
                        }
                    }
                }
            }
    W3 out{};
    double nrm = 0.0;
    for (int t = 0; t < L1 * L2 * L3; t++) { out.w[t] = acc[t].re; nrm += out.w[t] * out.w[t]; }
    nrm = csqrt_(nrm);
    for (int t = 0; t < L1 * L2 * L3; t++) out.w[t] /= nrm;
    return out;
}

struct CGTab { float cg[1225]; float c5[45]; };

constexpr CGTab build_cg_c() {
    CGTab P{};
    const int l1s[9]   = {0, 0, 0, 1, 1, 1, 2, 2, 2};
    const int l2s[9]   = {0, 1, 2, 0, 1, 2, 0, 1, 2};
    const int cgoff[9] = {0, 1, 10, 35, 44, 125, 350, 375, 600};
    for (int p = 0; p < 9; p++) {
        int l1 = l1s[p], l2 = l2s[p];
        int L1 = 2 * l1 + 1, L2 = 2 * l2 + 1, R = L1 * L2;
        int lmin = (l1 > l2) ? (l1 - l2) : (l2 - l1);
        int rof = 0;
        for (int l3 = lmin; l3 <= l1 + l2; l3++) {
            W3 w = wigner3j_c(l1, l2, l3);
            int L3 = 2 * l3 + 1;
            double sc = csqrt_(2.0 * l3 + 1.0);
            for (int a = 0; a < L1; a++)
                for (int b = 0; b < L2; b++)
                    for (int nn = 0; nn < L3; nn++)
                        P.cg[cgoff[p] + (a * L2 + b) * R + rof + nn] =
                            (float)(w.w[(a * L2 + b) * L3 + nn] * sc);
            rof += L3;
        }
    }
    W3 w = wigner3j_c(1, 1, 2);
    double s5 = csqrt_(5.0);
    for (int t = 0; t < 45; t++) P.c5[t] = (float)(w.w[t] * s5);
    return P;
}

constexpr CGTab CGH = build_cg_c();

template <int I> struct CGC { static constexpr float v = CGH.cg[I]; };
template <int I> struct C5C { static constexpr float v = CGH.c5[I]; };

// ----------------------------------------------------------------------------
// Index-sequence machinery
// ----------------------------------------------------------------------------
template <int... Is> struct iseq {};
template <int N, int... Is> struct mkseq_ : mkseq_<N - 1, N - 1, Is...> {};
template <int... Is> struct mkseq_<0, Is...> { using type = iseq<Is...>; };
template <int N> using mkseq = typename mkseq_<N>::type;

template <int IDX>
__device__ __forceinline__ float cgfma(float x, float s) {
    constexpr float c = CGC<IDX>::v;
    if constexpr (c == 0.0f) return s;
    else return fmaf(c, x, s);            // FFMA-imm form, rt=1
}
template <int IDX>
__device__ __forceinline__ float c5fma(float x, float s) {
    constexpr float c = C5C<IDX>::v;
    if constexpr (c == 0.0f) return s;
    else return fmaf(c, x, s);
}

template <int CGOFF, int R, int RIDX, int... ABs>
__device__ __forceinline__ void cg_step(float xv, float* __restrict__ Hz, iseq<ABs...>) {
    ((Hz[ABs] = cgfma<CGOFF + ABs * R + RIDX>(xv, Hz[ABs])), ...);
}
template <int CGOFF, int R, int... Rs>
__device__ __forceinline__ void cg_stream(const float* __restrict__ x,
                                          float* __restrict__ Hz, iseq<Rs...>) {
    ((cg_step<CGOFF, R, Rs>(x[Rs], Hz, mkseq<R>{})), ...);
}

// ----------------------------------------------------------------------------
// Pair transform on a register buffer.
// ----------------------------------------------------------------------------
template <int L1, int L2, int NCH, int CGOFF>
__device__ __forceinline__ void do_pair(float* __restrict__ x,
                                        const float* __restrict__ Dl,
                                        const float* __restrict__ Dr) {
    constexpr int R = L1 * L2;
#pragma unroll
    for (int q = 0; q < NCH; ++q) {
        float Hz[R];
#pragma unroll
        for (int ab = 0; ab < R; ++ab) Hz[ab] = 0.f;
        cg_stream<CGOFF, R>(x + q * R, Hz, mkseq<R>{});
#pragma unroll
        for (int l = 0; l < L1; ++l) {
            float T[L2];
#pragma unroll
            for (int b = 0; b < L2; ++b) {
                if constexpr (L1 == 1) {
                    T[b] = Hz[b];
                } else {
                    float s = 0.f;
#pragma unroll
                    for (int m = 0; m < L1; ++m)
                        s = fmaf(Dl[l * L1 + m], Hz[m * L2 + b], s);
                    T[b] = s;
                }
            }
#pragma unroll
            for (int k = 0; k < L2; ++k) {
                if constexpr (L2 == 1) {
                    x[q * R + l * L2 + k] = T[0];
                } else {
                    float s = 0.f;
#pragma unroll
                    for (int o = 0; o < L2; ++o)
                        s = fmaf(T[o], Dr[k * L2 + o], s);
                    x[q * R + l * L2 + k] = s;
                }
            }
        }
    }
}

// ----------------------------------------------------------------------------
// D builders (C5 coefficients as immediates).
// ----------------------------------------------------------------------------
template <int N, int N1>
__device__ __forceinline__ float u_ent(const float* __restrict__ d1row) {
    float s = 0.f;
    s = c5fma<(N1 * 3 + 0) * 5 + N>(d1row[0], s);
    s = c5fma<(N1 * 3 + 1) * 5 + N>(d1row[1], s);
    s = c5fma<(N1 * 3 + 2) * 5 + N>(d1row[2], s);
    return s;
}
template <int M, int... MMs>
__device__ __forceinline__ float d2_ent(const float* __restrict__ E, iseq<MMs...>) {
    float s = 0.f;
    ((s = c5fma<MMs * 5 + M>(E[MMs], s)), ...);
    return s;
}
template <int N>
__device__ __forceinline__ void d2_col(const float* __restrict__ D1m, float* __restrict__ D2m) {
    float U[9];
#pragma unroll
    for (int m2 = 0; m2 < 3; ++m2) {
        U[m2 * 3 + 0] = u_ent<N, 0>(D1m + m2 * 3);
        U[m2 * 3 + 1] = u_ent<N, 1>(D1m + m2 * 3);
        U[m2 * 3 + 2] = u_ent<N, 2>(D1m + m2 * 3);
    }
    float E[9];
#pragma unroll
    for (int m1 = 0; m1 < 3; ++m1)
#pragma unroll
        for (int m2 = 0; m2 < 3; ++m2) {
            float s = 0.f;
#pragma unroll
            for (int n1 = 0; n1 < 3; ++n1)
                s = fmaf(D1m[m1 * 3 + n1], U[m2 * 3 + n1], s);
            E[m1 * 3 + m2] = s;
        }
    D2m[0 * 5 + N] = d2_ent<0>(E, mkseq<9>{});
    D2m[1 * 5 + N] = d2_ent<1>(E, mkseq<9>{});
    D2m[2 * 5 + N] = d2_ent<2>(E, mkseq<9>{});
    D2m[3 * 5 + N] = d2_ent<3>(E, mkseq<9>{});
    D2m[4 * 5 + N] = d2_ent<4>(E, mkseq<9>{});
}

// ----------------------------------------------------------------------------
// Float4 streaming row I/O on SMEM with carry registers (OFF local to phase).
// ----------------------------------------------------------------------------
template <int OFF, int SIZE>
__device__ __forceinline__ void load_x(const float4* __restrict__ g, float4& ic,
                                       float* __restrict__ x) {
    constexpr int LO = OFF / 4;
    constexpr int HI = (OFF + SIZE - 1) / 4;
    constexpr int PH = OFF % 4;
#pragma unroll
    for (int f = LO; f <= HI; ++f) {
        float4 v = (f == LO && PH != 0) ? ic : g[f];
        float vv[4] = {v.x, v.y, v.z, v.w};
#pragma unroll
        for (int j = 0; j < 4; ++j) {
            int c = 4 * f + j;
            if (c >= OFF && c < OFF + SIZE) x[c - OFF] = vv[j];
        }
        if (f == HI) ic = v;   // carry boundary f4 to next pair
    }
}

template <int OFF, int SIZE>
__device__ __forceinline__ void store_y(float4* __restrict__ g, float4& oc,
                                        const float* __restrict__ x) {
    constexpr int LO = OFF / 4;
    constexpr int HI = (OFF + SIZE - 1) / 4;
    constexpr int PH = OFF % 4;
    constexpr int PE = (OFF + SIZE) % 4;
#pragma unroll
    for (int f = LO; f <= HI; ++f) {
        float vv[4];
#pragma unroll
        for (int j = 0; j < 4; ++j) {
            int c = 4 * f + j;
            vv[j] = (c >= OFF && c < OFF + SIZE) ? x[c - OFF] : 0.f;
        }
        if (f == LO && PH != 0) {          // merge leading floats from carry
            float ov[4] = {oc.x, oc.y, oc.z, oc.w};
#pragma unroll
            for (int j = 0; j < PH; ++j) vv[j] = ov[j];
        }
        if (f == HI && PE != 0) {
            oc = make_float4(vv[0], vv[1], vv[2], vv[3]);   // hold partial
        } else {
            g[f] = make_float4(vv[0], vv[1], vv[2], vv[3]);
        }
    }
}

// ----------------------------------------------------------------------------
// cp.async helpers
// ----------------------------------------------------------------------------
__device__ __forceinline__ void cp16(void* smem_dst, const void* gsrc) {
    uint32_t sa = (uint32_t)__cvta_generic_to_shared(smem_dst);
    asm volatile("cp.async.cg.shared.global [%0], [%1], 16;" :: "r"(sa), "l"(gsrc));
}
__device__ __forceinline__ void cp_commit() {
    asm volatile("cp.async.commit_group;");
}
template <int N>
__device__ __forceinline__ void cp_wait() {
    asm volatile("cp.async.wait_group %0;" :: "n"(N));
}

// ----------------------------------------------------------------------------
// Kernel: PERSISTENT CTAs, cross-tile cp.async pipeline, all-f4 smem compute.
// Each CTA loops over tiles strided by gridDim.x; next tile's loads are issued
// immediately after the current phase's buffer is drained, so DRAM request
// issue is continuous across tile boundaries.
// ----------------------------------------------------------------------------
__global__ void __launch_bounds__(NTHREADS, 4)
e3_kernel(const float* __restrict__ feat, const float* __restrict__ vec,
          float* __restrict__ out, int n, int ntiles) {
    extern __shared__ float4 sm4[];
    float4* bufA = sm4;                 // EPB x S4
    float4* bufB = sm4 + EPB * S4;      // EPB x S4
    const int tid = threadIdx.x;
    const int tstride = gridDim.x;

    const float4* g4 = reinterpret_cast<const float4*>(feat);
    float4* o4 = reinterpret_cast<float4*>(out);

    int tile = blockIdx.x;
    if (tile >= ntiles) return;

    auto issueA = [&](int t) {
        const int e0 = t * EPB;
        const int nA = min(EPB, n - e0) * A_F4;
        for (int i = tid; i < nA; i += NTHREADS) {
            int r = i / A_F4, c = i - r * A_F4;
            cp16(&bufA[r * S4 + c], &g4[(size_t)(e0 + r) * 49 + c]);
        }
    };
    auto issueB = [&](int t) {
        const int e0 = t * EPB;
        const int nB = min(EPB, n - e0) * B_F4;
        for (int i = tid; i < nB; i += NTHREADS) {
            int r = i / B_F4, c = i - r * B_F4;
            cp16(&bufB[r * S4 + c], &g4[(size_t)(e0 + r) * 49 + A_F4 + c]);
        }
    };

    // registers holding the direction for the CURRENT tile (prefetched)
    float vx = 0.f, vy = 1.f, vz = 0.f;
    auto loadvec = [&](int t) {
        const int e0 = t * EPB;
        if (tid < min(EPB, n - e0)) {
            const int e = e0 + tid;
            vx = vec[3 * e + 0]; vy = vec[3 * e + 1]; vz = vec[3 * e + 2];
        } else { vx = 0.f; vy = 1.f; vz = 0.f; }
    };

    // ---- prolog: first tile's loads + vec ----
    issueA(tile); cp_commit();
    issueB(tile); cp_commit();
    loadvec(tile);

    while (true) {
        const int next = tile + tstride;
        const int e0 = tile * EPB;
        const int nvalid = min(EPB, n - e0);
        const int nA = nvalid * A_F4;
        const int nB = nvalid * B_F4;

        // ---- build D1, D2 for this tile (vec already in registers) ----
        float D1m[9], D2m[25];
        {
            float tx = vx, ty = vy, tz = vz;
            float inv = rsqrtf(fmaf(tx, tx, fmaf(ty, ty, tz * tz)));
            tx *= inv; ty *= inv; tz *= inv;
            float cb = fminf(1.f, fmaxf(-1.f, ty));
            float sb = sqrtf(fmaxf(0.f, 1.f - cb * cb));
            float rho2 = fmaf(tx, tx, tz * tz);
            float ca, sa;
            if (rho2 > 0.f) {
                float ir = rsqrtf(rho2);
                ca = tz * ir; sa = tx * ir;
            } else { ca = 1.f; sa = 0.f; }
            D1m[0] = ca;   D1m[1] = sa * sb; D1m[2] = sa * cb;
            D1m[3] = 0.f;  D1m[4] = cb;      D1m[5] = -sb;
            D1m[6] = -sa;  D1m[7] = ca * sb; D1m[8] = ca * cb;
            d2_col<0>(D1m, D2m);
            d2_col<1>(D1m, D2m);
            d2_col<2>(D1m, D2m);
            d2_col<3>(D1m, D2m);
            d2_col<4>(D1m, D2m);
        }

        // ================= Phase A: cols [0,96) =================
        cp_wait<1>();          // A landed (older group); B may be in flight
        __syncthreads();
        if (tid < nvalid) {
            float4* row4 = bufA + tid * S4;
            float4 ic = make_float4(0.f, 0.f, 0.f, 0.f);
            float4 oc = ic;
            float x[36];
            load_x<0, 9>(row4, ic, x);   do_pair<1, 1, 9, 0  >(x, D1m, D1m); store_y<0, 9>(row4, oc, x);
            load_x<9, 18>(row4, ic, x);  do_pair<1, 3, 6, 1  >(x, D1m, D1m); store_y<9, 18>(row4, oc, x);
            load_x<27, 15>(row4, ic, x); do_pair<1, 5, 3, 10 >(x, D1m, D2m); store_y<27, 15>(row4, oc, x);
            load_x<42, 18>(row4, ic, x); do_pair<3, 1, 6, 35 >(x, D1m, D1m); store_y<42, 18>(row4, oc, x);
            load_x<60, 36>(row4, ic, x); do_pair<3, 3, 4, 44 >(x, D1m, D1m); store_y<60, 36>(row4, oc, x);
        }
        __syncthreads();
        // store A, then immediately refill bufA for the next tile.
        // Safe: the cp.async below uses the SAME i->cell mapping as this store
        // loop, so each thread only overwrites cells it has already read.
        for (int i = tid; i < nA; i += NTHREADS) {
            int r = i / A_F4, c = i - r * A_F4;
            o4[(size_t)(e0 + r) * 49 + c] = bufA[r * S4 + c];
        }
        if (next < ntiles) issueA(next);
        cp_commit();           // group order: ... B_cur, A_next

        // ================= Phase B: cols [96,196) =================
        cp_wait<1>();          // all but most recent done => B_cur landed
        __syncthreads();
        if (tid < nvalid) {
            float4* row4 = bufB + tid * S4;
            float4 ic = make_float4(0.f, 0.f, 0.f, 0.f);
            float4 oc = ic;
            float x[36];
            load_x<0, 30>(row4, ic, x);  do_pair<3, 5, 2, 125>(x, D1m, D2m); store_y<0, 30>(row4, oc, x);
            load_x<30, 15>(row4, ic, x); do_pair<5, 1, 3, 350>(x, D2m, D1m); store_y<30, 15>(row4, oc, x);
            load_x<45, 30>(row4, ic, x); do_pair<5, 3, 2, 375>(x, D2m, D1m); store_y<45, 30>(row4, oc, x);
            load_x<75, 25>(row4, ic, x); do_pair<5, 5, 1, 600>(x, D2m, D2m); store_y<75, 25>(row4, oc, x);
        }
        if (next < ntiles) loadvec(next);   // prefetch next tile's direction
        __syncthreads();
        for (int i = tid; i < nB; i += NTHREADS) {
            int r = i / B_F4, c = i - r * B_F4;
            o4[(size_t)(e0 + r) * 49 + A_F4 + c] = bufB[r * S4 + c];
        }
        if (next < ntiles) issueB(next);
        cp_commit();           // group order: A_next, B_next

        if (next >= ntiles) break;
        tile = next;
    }
}

// ----------------------------------------------------------------------------
// Launch
// ----------------------------------------------------------------------------
extern "C" void kernel_launch(void* const* d_in, const int* in_sizes, int n_in,
                              void* d_out, int out_size) {
    (void)n_in; (void)out_size;
    const float* feat = (const float*)d_in[0];
    const float* vec  = (const float*)d_in[1];
    float* out = (float*)d_out;
    const int n = in_sizes[0] / NF;
    const int ntiles = (n + EPB - 1) / EPB;

    cudaFuncSetAttribute(e3_kernel, cudaFuncAttributeMaxDynamicSharedMemorySize, SMEM_BYTES);
    int blocks = ntiles < MAXBLOCKS ? ntiles : MAXBLOCKS;
    e3_kernel<<<blocks, NTHREADS, SMEM_BYTES>>>(feat, vec, out, n, ntiles);
}

// round 15
// speedup vs baseline: 1.2025x; 1.2025x over previous
#include <cuda_runtime.h>
#include <cuda_bf16.h>
#include <cstdint>

// ----------------------------------------------------------------------------
// Constants
// ----------------------------------------------------------------------------
#define NF       196
#define EPB      32
#define NTHREADS 32
#define S4       25          // float4 stride per smem row (400B: conflict-free f4 access)
#define A_F4     24          // phase A: cols [0,96)   -> f4 0..23
#define B_F4     25          // phase B: cols [96,196) -> f4 24..48
#define SMEM_BYTES (2 * EPB * S4 * 16)

// pairs (offset,size): ss 0,9  sp 9,18  sd 27,15  ps 42,18  pp 60,36
//                      pd 96,30  ds 126,15  dp 141,30  dd 171,25
// cg offsets: ss0 sp1 sd10 ps35 pp44 pd125 ds350 dp375 dd600

// ----------------------------------------------------------------------------
// Compile-time CG computation: constexpr float64 mirror of the numpy reference.
// ----------------------------------------------------------------------------
struct CD { double re, im; };
constexpr CD cadd(CD a, CD b) { return {a.re + b.re, a.im + b.im}; }
constexpr CD cmulc(CD a, CD b) { return {a.re * b.re - a.im * b.im, a.re * b.im + a.im * b.re}; }
constexpr CD cscale(CD a, double s) { return {a.re * s, a.im * s}; }
constexpr CD cconj(CD a) { return {a.re, -a.im}; }
constexpr bool ciszero(CD a) { return a.re == 0.0 && a.im == 0.0; }

constexpr double cfact(int n) { double r = 1.0; for (int i = 2; i <= n; i++) r *= i; return r; }

constexpr double csqrt_(double x) {
    if (x <= 0.0) return 0.0;
    double y = x > 1.0 ? x : 1.0;
    for (int i = 0; i < 80; i++) {
        double ny = 0.5 * (y + x / y);
        if (ny == y) break;
        y = ny;
    }
    return y;
}

constexpr double su2_cg_c(int j1, int j2, int j3, int m1, int m2, int m3) {
    if (m3 != m1 + m2) return 0.0;
    int vmin = -j1 + j2 + m3;
    if (-j1 + m1 > vmin) vmin = -j1 + m1;
    if (0 > vmin) vmin = 0;
    int vmax = j2 + j3 + m1;
    if (j3 - j1 + j2 < vmax) vmax = j3 - j1 + j2;
    if (j3 + m3 < vmax) vmax = j3 + m3;
    double C = csqrt_((2.0 * j3 + 1.0) * cfact(j3 + j1 - j2) * cfact(j3 - j1 + j2)
                      * cfact(j1 + j2 - j3) * cfact(j3 + m3) * cfact(j3 - m3)
                      / (cfact(j1 + j2 + j3 + 1) * cfact(j1 - m1) * cfact(j1 + m1)
                         * cfact(j2 - m2) * cfact(j2 + m2)));
    double S = 0.0;
    for (int v = vmin; v <= vmax; v++) {
        double sg = ((v + j2 + m2) & 1) ? -1.0 : 1.0;
        S += sg * cfact(j2 + j3 + m1 - v) * cfact(j1 - m1 + v)
             / (cfact(v) * cfact(j3 - j1 + j2 - v) * cfact(j3 + m3 - v)
                * cfact(v + j1 - j2 - m3));
    }
    return C * S;
}

struct QM { CD q[81]; };

constexpr QM change_basis_c(int l) {
    QM Q{};
    int L = 2 * l + 1;
    for (int i = 0; i < L * L; i++) Q.q[i] = CD{0, 0};
    double is2 = 1.0 / csqrt_(2.0);
    for (int m = -l; m < 0; m++) {
        Q.q[(l + m) * L + (l - m)] = CD{is2, 0};
        Q.q[(l + m) * L + (l + m)] = CD{0, -is2};
    }
    Q.q[l * L + l] = CD{1, 0};
    for (int m = 1; m <= l; m++) {
        double sg = (m & 1) ? -1.0 : 1.0;
        Q.q[(l + m) * L + (l + m)] = CD{sg * is2, 0};
        Q.q[(l + m) * L + (l - m)] = CD{0, sg * is2};
    }
    CD ph{1, 0};
    for (int k = 0; k < l; k++) ph = cmulc(ph, CD{0, -1});   // (-i)^l
    for (int i = 0; i < L * L; i++) Q.q[i] = cmulc(Q.q[i], ph);
    return Q;
}

struct W3 { double w[225]; };

constexpr W3 wigner3j_c(int l1, int l2, int l3) {
    int L1 = 2 * l1 + 1, L2 = 2 * l2 + 1, L3 = 2 * l3 + 1;
    QM Q1 = change_basis_c(l1), Q2 = change_basis_c(l2), Q3 = change_basis_c(l3);
    CD acc[225]{};
    for (int t = 0; t < 225; t++) acc[t] = CD{0, 0};
    for (int i = 0; i < L1; i++)
        for (int k = 0; k < L2; k++)
            for (int n = 0; n < L3; n++) {
                double c = su2_cg_c(l1, l2, l3, i - l1, k - l2, n - l3);
                if (c == 0.0) continue;
                for (int j = 0; j < L1; j++) {
                    CD q1 = Q1.q[i * L1 + j];
                    if (ciszero(q1)) continue;
                    for (int l = 0; l < L2; l++) {
                        CD q2 = Q2.q[k * L2 + l];
                        if (ciszero(q2)) continue;
                        CD q12 = cmulc(q1, q2);
                        for (int m = 0; m < L3; m++) {
                            CD q3 = Q3.q[n * L3 + m];
                            if (ciszero(q3)) continue;
                            CD t = cmulc(q12, cconj(q3));
                            int o = (j * L2 + l) * L3 + m;
                            acc[o] = cadd(acc[o], cscale(t, c));
                        }
                    }
                }
            }
    W3 out{};
    double nrm = 0.0;
    for (int t = 0; t < L1 * L2 * L3; t++) { out.w[t] = acc[t].re; nrm += out.w[t] * out.w[t]; }
    nrm = csqrt_(nrm);
    for (int t = 0; t < L1 * L2 * L3; t++) out.w[t] /= nrm;
    return out;
}

struct CGTab { float cg[1225]; float c5[45]; };

constexpr CGTab build_cg_c() {
    CGTab P{};
    const int l1s[9]   = {0, 0, 0, 1, 1, 1, 2, 2, 2};
    const int l2s[9]   = {0, 1, 2, 0, 1, 2, 0, 1, 2};
    const int cgoff[9] = {0, 1, 10, 35, 44, 125, 350, 375, 600};
    for (int p = 0; p < 9; p++) {
        int l1 = l1s[p], l2 = l2s[p];
        int L1 = 2 * l1 + 1, L2 = 2 * l2 + 1, R = L1 * L2;
        int lmin = (l1 > l2) ? (l1 - l2) : (l2 - l1);
        int rof = 0;
        for (int l3 = lmin; l3 <= l1 + l2; l3++) {
            W3 w = wigner3j_c(l1, l2, l3);
            int L3 = 2 * l3 + 1;
            double sc = csqrt_(2.0 * l3 + 1.0);
            for (int a = 0; a < L1; a++)
                for (int b = 0; b < L2; b++)
                    for (int nn = 0; nn < L3; nn++)
                        P.cg[cgoff[p] + (a * L2 + b) * R + rof + nn] =
                            (float)(w.w[(a * L2 + b) * L3 + nn] * sc);
            rof += L3;
        }
    }
    W3 w = wigner3j_c(1, 1, 2);
    double s5 = csqrt_(5.0);
    for (int t = 0; t < 45; t++) P.c5[t] = (float)(w.w[t] * s5);
    return P;
}

constexpr CGTab CGH = build_cg_c();

template <int I> struct CGC { static constexpr float v = CGH.cg[I]; };
template <int I> struct C5C { static constexpr float v = CGH.c5[I]; };

// ----------------------------------------------------------------------------
// Index-sequence machinery
// ----------------------------------------------------------------------------
template <int... Is> struct iseq {};
template <int N, int... Is> struct mkseq_ : mkseq_<N - 1, N - 1, Is...> {};
template <int... Is> struct mkseq_<0, Is...> { using type = iseq<Is...>; };
template <int N> using mkseq = typename mkseq_<N>::type;

template <int IDX>
__device__ __forceinline__ float cgfma(float x, float s) {
    constexpr float c = CGC<IDX>::v;
    if constexpr (c == 0.0f) return s;
    else return fmaf(c, x, s);            // FFMA-imm form, rt=1
}
template <int IDX>
__device__ __forceinline__ float c5fma(float x, float s) {
    constexpr float c = C5C<IDX>::v;
    if constexpr (c == 0.0f) return s;
    else return fmaf(c, x, s);
}

template <int CGOFF, int R, int RIDX, int... ABs>
__device__ __forceinline__ void cg_step(float xv, float* __restrict__ Hz, iseq<ABs...>) {
    ((Hz[ABs] = cgfma<CGOFF + ABs * R + RIDX>(xv, Hz[ABs])), ...);
}
template <int CGOFF, int R, int... Rs>
__device__ __forceinline__ void cg_stream(const float* __restrict__ x,
                                          float* __restrict__ Hz, iseq<Rs...>) {
    ((cg_step<CGOFF, R, Rs>(x[Rs], Hz, mkseq<R>{})), ...);
}

// ----------------------------------------------------------------------------
// Pair transform on a register buffer.
// ----------------------------------------------------------------------------
template <int L1, int L2, int NCH, int CGOFF>
__device__ __forceinline__ void do_pair(float* __restrict__ x,
                                        const float* __restrict__ Dl,
                                        const float* __restrict__ Dr) {
    constexpr int R = L1 * L2;
#pragma unroll
    for (int q = 0; q < NCH; ++q) {
        float Hz[R];
#pragma unroll
        for (int ab = 0; ab < R; ++ab) Hz[ab] = 0.f;
        cg_stream<CGOFF, R>(x + q * R, Hz, mkseq<R>{});
#pragma unroll
        for (int l = 0; l < L1; ++l) {
            float T[L2];
#pragma unroll
            for (int b = 0; b < L2; ++b) {
                if constexpr (L1 == 1) {
                    T[b] = Hz[b];
                } else {
                    float s = 0.f;
#pragma unroll
                    for (int m = 0; m < L1; ++m)
                        s = fmaf(Dl[l * L1 + m], Hz[m * L2 + b], s);
                    T[b] = s;
                }
            }
#pragma unroll
            for (int k = 0; k < L2; ++k) {
                if constexpr (L2 == 1) {
                    x[q * R + l * L2 + k] = T[0];
                } else {
                    float s = 0.f;
#pragma unroll
                    for (int o = 0; o < L2; ++o)
                        s = fmaf(T[o], Dr[k * L2 + o], s);
                    x[q * R + l * L2 + k] = s;
                }
            }
        }
    }
}

// ----------------------------------------------------------------------------
// D builders (C5 coefficients as immediates).
// ----------------------------------------------------------------------------
template <int N, int N1>
__device__ __forceinline__ float u_ent(const float* __restrict__ d1row) {
    float s = 0.f;
    s = c5fma<(N1 * 3 + 0) * 5 + N>(d1row[0], s);
    s = c5fma<(N1 * 3 + 1) * 5 + N>(d1row[1], s);
    s = c5fma<(N1 * 3 + 2) * 5 + N>(d1row[2], s);
    return s;
}
template <int M, int... MMs>
__device__ __forceinline__ float d2_ent(const float* __restrict__ E, iseq<MMs...>) {
    float s = 0.f;
    ((s = c5fma<MMs * 5 + M>(E[MMs], s)), ...);
    return s;
}
template <int N>
__device__ __forceinline__ void d2_col(const float* __restrict__ D1m, float* __restrict__ D2m) {
    float U[9];
#pragma unroll
    for (int m2 = 0; m2 < 3; ++m2) {
        U[m2 * 3 + 0] = u_ent<N, 0>(D1m + m2 * 3);
        U[m2 * 3 + 1] = u_ent<N, 1>(D1m + m2 * 3);
        U[m2 * 3 + 2] = u_ent<N, 2>(D1m + m2 * 3);
    }
    float E[9];
#pragma unroll
    for (int m1 = 0; m1 < 3; ++m1)
#pragma unroll
        for (int m2 = 0; m2 < 3; ++m2) {
            float s = 0.f;
#pragma unroll
            for (int n1 = 0; n1 < 3; ++n1)
                s = fmaf(D1m[m1 * 3 + n1], U[m2 * 3 + n1], s);
            E[m1 * 3 + m2] = s;
        }
    D2m[0 * 5 + N] = d2_ent<0>(E, mkseq<9>{});
    D2m[1 * 5 + N] = d2_ent<1>(E, mkseq<9>{});
    D2m[2 * 5 + N] = d2_ent<2>(E, mkseq<9>{});
    D2m[3 * 5 + N] = d2_ent<3>(E, mkseq<9>{});
    D2m[4 * 5 + N] = d2_ent<4>(E, mkseq<9>{});
}

// ----------------------------------------------------------------------------
// Float4 streaming row I/O on SMEM with carry registers (OFF local to phase).
// ----------------------------------------------------------------------------
template <int OFF, int SIZE>
__device__ __forceinline__ void load_x(const float4* __restrict__ g, float4& ic,
                                       float* __restrict__ x) {
    constexpr int LO = OFF / 4;
    constexpr int HI = (OFF + SIZE - 1) / 4;
    constexpr int PH = OFF % 4;
#pragma unroll
    for (int f = LO; f <= HI; ++f) {
        float4 v = (f == LO && PH != 0) ? ic : g[f];
        float vv[4] = {v.x, v.y, v.z, v.w};
#pragma unroll
        for (int j = 0; j < 4; ++j) {
            int c = 4 * f + j;
            if (c >= OFF && c < OFF + SIZE) x[c - OFF] = vv[j];
        }
        if (f == HI) ic = v;   // carry boundary f4 to next pair
    }
}

template <int OFF, int SIZE>
__device__ __forceinline__ void store_y(float4* __restrict__ g, float4& oc,
                                        const float* __restrict__ x) {
    constexpr int LO = OFF / 4;
    constexpr int HI = (OFF + SIZE - 1) / 4;
    constexpr int PH = OFF % 4;
    constexpr int PE = (OFF + SIZE) % 4;
#pragma unroll
    for (int f = LO; f <= HI; ++f) {
        float vv[4];
#pragma unroll
        for (int j = 0; j < 4; ++j) {
            int c = 4 * f + j;
            vv[j] = (c >= OFF && c < OFF + SIZE) ? x[c - OFF] : 0.f;
        }
        if (f == LO && PH != 0) {          // merge leading floats from carry
            float ov[4] = {oc.x, oc.y, oc.z, oc.w};
#pragma unroll
            for (int j = 0; j < PH; ++j) vv[j] = ov[j];
        }
        if (f == HI && PE != 0) {
            oc = make_float4(vv[0], vv[1], vv[2], vv[3]);   // hold partial
        } else {
            g[f] = make_float4(vv[0], vv[1], vv[2], vv[3]);
        }
    }
}

// ----------------------------------------------------------------------------
// cp.async helpers
// ----------------------------------------------------------------------------
__device__ __forceinline__ void cp16(void* smem_dst, const void* gsrc) {
    uint32_t sa = (uint32_t)__cvta_generic_to_shared(smem_dst);
    asm volatile("cp.async.cg.shared.global [%0], [%1], 16;" :: "r"(sa), "l"(gsrc));
}
__device__ __forceinline__ void cp_commit() {
    asm volatile("cp.async.commit_group;");
}
template <int N>
__device__ __forceinline__ void cp_wait() {
    asm volatile("cp.async.wait_group %0;" :: "n"(N));
}

// ----------------------------------------------------------------------------
// Kernel: double-buffered phases, cp.async prefetch, all-f4 smem compute.
// EPB=32 -> 25.6 KB smem -> 8 independent CTA pipelines per SM.
// ----------------------------------------------------------------------------
__global__ void __launch_bounds__(NTHREADS, 8)
e3_kernel(const float* __restrict__ feat, const float* __restrict__ vec,
          float* __restrict__ out, int n) {
    extern __shared__ float4 sm4[];
    float4* bufA = sm4;                 // EPB x S4
    float4* bufB = sm4 + EPB * S4;      // EPB x S4
    const int tid = threadIdx.x;
    const int e0 = blockIdx.x * EPB;
    const int nvalid = min(EPB, n - e0);

    const float4* g4 = reinterpret_cast<const float4*>(feat);
    float4* o4 = reinterpret_cast<float4*>(out);

    // ---- issue BOTH phase loads up front (async) ----
    const int nA = nvalid * A_F4;
    for (int i = tid; i < nA; i += NTHREADS) {
        int r = i / A_F4, c = i - r * A_F4;
        cp16(&bufA[r * S4 + c], &g4[(size_t)(e0 + r) * 49 + c]);
    }
    cp_commit();   // group: A
    const int nB = nvalid * B_F4;
    for (int i = tid; i < nB; i += NTHREADS) {
        int r = i / B_F4, c = i - r * B_F4;
        cp16(&bufB[r * S4 + c], &g4[(size_t)(e0 + r) * 49 + A_F4 + c]);
    }
    cp_commit();   // group: B

    // ---- build D1, D2 once (overlaps the async loads) ----
    float D1m[9], D2m[25];
    {
        float vx = 0.f, vy = 1.f, vz = 0.f;
        if (tid < nvalid) {
            const int e = e0 + tid;
            vx = vec[3 * e + 0]; vy = vec[3 * e + 1]; vz = vec[3 * e + 2];
        }
        float inv = rsqrtf(fmaf(vx, vx, fmaf(vy, vy, vz * vz)));
        vx *= inv; vy *= inv; vz *= inv;
        float cb = fminf(1.f, fmaxf(-1.f, vy));
        float sb = sqrtf(fmaxf(0.f, 1.f - cb * cb));
        float rho2 = fmaf(vx, vx, vz * vz);
        float ca, sa;
        if (rho2 > 0.f) {
            float ir = rsqrtf(rho2);
            ca = vz * ir; sa = vx * ir;
        } else { ca = 1.f; sa = 0.f; }
        D1m[0] = ca;   D1m[1] = sa * sb; D1m[2] = sa * cb;
        D1m[3] = 0.f;  D1m[4] = cb;      D1m[5] = -sb;
        D1m[6] = -sa;  D1m[7] = ca * sb; D1m[8] = ca * cb;
        d2_col<0>(D1m, D2m);
        d2_col<1>(D1m, D2m);
        d2_col<2>(D1m, D2m);
        d2_col<3>(D1m, D2m);
        d2_col<4>(D1m, D2m);
    }

    // ================= Phase A: cols [0,96) =================
    cp_wait<1>();          // A landed; B still in flight
    __syncthreads();
    if (tid < nvalid) {
        float4* row4 = bufA + tid * S4;
        float4 ic = make_float4(0.f, 0.f, 0.f, 0.f);
        float4 oc = ic;
        float x[36];
        load_x<0, 9>(row4, ic, x);   do_pair<1, 1, 9, 0  >(x, D1m, D1m); store_y<0, 9>(row4, oc, x);
        load_x<9, 18>(row4, ic, x);  do_pair<1, 3, 6, 1  >(x, D1m, D1m); store_y<9, 18>(row4, oc, x);
        load_x<27, 15>(row4, ic, x); do_pair<1, 5, 3, 10 >(x, D1m, D2m); store_y<27, 15>(row4, oc, x);
        load_x<42, 18>(row4, ic, x); do_pair<3, 1, 6, 35 >(x, D1m, D1m); store_y<42, 18>(row4, oc, x);
        load_x<60, 36>(row4, ic, x); do_pair<3, 3, 4, 44 >(x, D1m, D1m); store_y<60, 36>(row4, oc, x);
    }
    __syncthreads();
    for (int i = tid; i < nA; i += NTHREADS) {
        int r = i / A_F4, c = i - r * A_F4;
        o4[(size_t)(e0 + r) * 49 + c] = bufA[r * S4 + c];
    }

    // ================= Phase B: cols [96,196) =================
    cp_wait<0>();          // B landed
    __syncthreads();
    if (tid < nvalid) {
        float4* row4 = bufB + tid * S4;
        float4 ic = make_float4(0.f, 0.f, 0.f, 0.f);
        float4 oc = ic;
        float x[36];
        load_x<0, 30>(row4, ic, x);  do_pair<3, 5, 2, 125>(x, D1m, D2m); store_y<0, 30>(row4, oc, x);
        load_x<30, 15>(row4, ic, x); do_pair<5, 1, 3, 350>(x, D2m, D1m); store_y<30, 15>(row4, oc, x);
        load_x<45, 30>(row4, ic, x); do_pair<5, 3, 2, 375>(x, D2m, D1m); store_y<45, 30>(row4, oc, x);
        load_x<75, 25>(row4, ic, x); do_pair<5, 5, 1, 600>(x, D2m, D2m); store_y<75, 25>(row4, oc, x);
    }
    __syncthreads();
    for (int i = tid; i < nB; i += NTHREADS) {
        int r = i / B_F4, c = i - r * B_F4;
        o4[(size_t)(e0 + r) * 49 + A_F4 + c] = bufB[r * S4 + c];
    }
}

// ----------------------------------------------------------------------------
// Launch
// ----------------------------------------------------------------------------
extern "C" void kernel_launch(void* const* d_in, const int* in_sizes, int n_in,
                              void* d_out, int out_size) {
    (void)n_in; (void)out_size;
    const float* feat = (const float*)d_in[0];
    const float* vec  = (const float*)d_in[1];
    float* out = (float*)d_out;
    const int n = in_sizes[0] / NF;

    cudaFuncSetAttribute(e3_kernel, cudaFuncAttributeMaxDynamicSharedMemorySize, SMEM_BYTES);
    int blocks = (n + EPB - 1) / EPB;
    e3_kernel<<<blocks, NTHREADS, SMEM_BYTES>>>(feat, vec, out, n);
}

// round 16
// speedup vs baseline: 1.2070x; 1.0037x over previous
#include <cuda_runtime.h>
#include <cuda_bf16.h>
#include <cstdint>

// ----------------------------------------------------------------------------
// Constants
// ----------------------------------------------------------------------------
#define NF       196
#define EPB      32
#define NTHREADS 64          // warp0: phase A compute, warp1: phase B compute
#define S4       25          // float4 stride per smem row (400B: conflict-free f4 access)
#define A_F4     24          // phase A: cols [0,96)   -> f4 0..23
#define B_F4     25          // phase B: cols [96,196) -> f4 24..48
#define SMEM_BYTES (2 * EPB * S4 * 16)

// pairs (offset,size): ss 0,9  sp 9,18  sd 27,15  ps 42,18  pp 60,36
//                      pd 96,30  ds 126,15  dp 141,30  dd 171,25
// cg offsets: ss0 sp1 sd10 ps35 pp44 pd125 ds350 dp375 dd600

// ----------------------------------------------------------------------------
// Compile-time CG computation: constexpr float64 mirror of the numpy reference.
// ----------------------------------------------------------------------------
struct CD { double re, im; };
constexpr CD cadd(CD a, CD b) { return {a.re + b.re, a.im + b.im}; }
constexpr CD cmulc(CD a, CD b) { return {a.re * b.re - a.im * b.im, a.re * b.im + a.im * b.re}; }
constexpr CD cscale(CD a, double s) { return {a.re * s, a.im * s}; }
constexpr CD cconj(CD a) { return {a.re, -a.im}; }
constexpr bool ciszero(CD a) { return a.re == 0.0 && a.im == 0.0; }

constexpr double cfact(int n) { double r = 1.0; for (int i = 2; i <= n; i++) r *= i; return r; }

constexpr double csqrt_(double x) {
    if (x <= 0.0) return 0.0;
    double y = x > 1.0 ? x : 1.0;
    for (int i = 0; i < 80; i++) {
        double ny = 0.5 * (y + x / y);
        if (ny == y) break;
        y = ny;
    }
    return y;
}

constexpr double su2_cg_c(int j1, int j2, int j3, int m1, int m2, int m3) {
    if (m3 != m1 + m2) return 0.0;
    int vmin = -j1 + j2 + m3;
    if (-j1 + m1 > vmin) vmin = -j1 + m1;
    if (0 > vmin) vmin = 0;
    int vmax = j2 + j3 + m1;
    if (j3 - j1 + j2 < vmax) vmax = j3 - j1 + j2;
    if (j3 + m3 < vmax) vmax = j3 + m3;
    double C = csqrt_((2.0 * j3 + 1.0) * cfact(j3 + j1 - j2) * cfact(j3 - j1 + j2)
                      * cfact(j1 + j2 - j3) * cfact(j3 + m3) * cfact(j3 - m3)
                      / (cfact(j1 + j2 + j3 + 1) * cfact(j1 - m1) * cfact(j1 + m1)
                         * cfact(j2 - m2) * cfact(j2 + m2)));
    double S = 0.0;
    for (int v = vmin; v <= vmax; v++) {
        double sg = ((v + j2 + m2) & 1) ? -1.0 : 1.0;
        S += sg * cfact(j2 + j3 + m1 - v) * cfact(j1 - m1 + v)
             / (cfact(v) * cfact(j3 - j1 + j2 - v) * cfact(j3 + m3 - v)
                * cfact(v + j1 - j2 - m3));
    }
    return C * S;
}

struct QM { CD q[81]; };

constexpr QM change_basis_c(int l) {
    QM Q{};
    int L = 2 * l + 1;
    for (int i = 0; i < L * L; i++) Q.q[i] = CD{0, 0};
    double is2 = 1.0 / csqrt_(2.0);
    for (int m = -l; m < 0; m++) {
        Q.q[(l + m) * L + (l - m)] = CD{is2, 0};
        Q.q[(l + m) * L + (l + m)] = CD{0, -is2};
    }
    Q.q[l * L + l] = CD{1, 0};
    for (int m = 1; m <= l; m++) {
        double sg = (m & 1) ? -1.0 : 1.0;
        Q.q[(l + m) * L + (l + m)] = CD{sg * is2, 0};
        Q.q[(l + m) * L + (l - m)] = CD{0, sg * is2};
    }
    CD ph{1, 0};
    for (int k = 0; k < l; k++) ph = cmulc(ph, CD{0, -1});   // (-i)^l
    for (int i = 0; i < L * L; i++) Q.q[i] = cmulc(Q.q[i], ph);
    return Q;
}

struct W3 { double w[225]; };

constexpr W3 wigner3j_c(int l1, int l2, int l3) {
    int L1 = 2 * l1 + 1, L2 = 2 * l2 + 1, L3 = 2 * l3 + 1;
    QM Q1 = change_basis_c(l1), Q2 = change_basis_c(l2), Q3 = change_basis_c(l3);
    CD acc[225]{};
    for (int t = 0; t < 225; t++) acc[t] = CD{0, 0};
    for (int i = 0; i < L1; i++)
        for (int k = 0; k < L2; k++)
            for (int n = 0; n < L3; n++) {
                double c = su2_cg_c(l1, l2, l3, i - l1, k - l2, n - l3);
                if (c == 0.0) continue;
                for (int j = 0; j < L1; j++) {
                    CD q1 = Q1.q[i * L1 + j];
                    if (ciszero(q1)) continue;
                    for (int l = 0; l < L2; l++) {
                        CD q2 = Q2.q[k * L2 + l];
                        if (ciszero(q2)) continue;
                        CD q12 = cmulc(q1, q2);
                        for (int m = 0; m < L3; m++) {
                            CD q3 = Q3.q[n * L3 + m];
                            if (ciszero(q3)) continue;
                            CD t = cmulc(q12, cconj(q3));
                            int o = (j * L2 + l) * L3 + m;
                            acc[o] = cadd(acc[o], cscale(t, c));
                        }
                    }
                }
            }
    W3 out{};
    double nrm = 0.0;
    for (int t = 0; t < L1 * L2 * L3; t++) { out.w[t] = acc[t].re; nrm += out.w[t] * out.w[t]; }
    nrm = csqrt_(nrm);
    for (int t = 0; t < L1 * L2 * L3; t++) out.w[t] /= nrm;
    return out;
}

struct CGTab { float cg[1225]; float c5[45]; };

constexpr CGTab build_cg_c() {
    CGTab P{};
    const int l1s[9]   = {0, 0, 0, 1, 1, 1, 2, 2, 2};
    const int l2s[9]   = {0, 1, 2, 0, 1, 2, 0, 1, 2};
    const int cgoff[9] = {0, 1, 10, 35, 44, 125, 350, 375, 600};
    for (int p = 0; p < 9; p++) {
        int l1 = l1s[p], l2 = l2s[p];
        int L1 = 2 * l1 + 1, L2 = 2 * l2 + 1, R = L1 * L2;
        int lmin = (l1 > l2) ? (l1 - l2) : (l2 - l1);
        int rof = 0;
        for (int l3 = lmin; l3 <= l1 + l2; l3++) {
            W3 w = wigner3j_c(l1, l2, l3);
            int L3 = 2 * l3 + 1;
            double sc = csqrt_(2.0 * l3 + 1.0);
            for (int a = 0; a < L1; a++)
                for (int b = 0; b < L2; b++)
                    for (int nn = 0; nn < L3; nn++)
                        P.cg[cgoff[p] + (a * L2 + b) * R + rof + nn] =
                            (float)(w.w[(a * L2 + b) * L3 + nn] * sc);
            rof += L3;
        }
    }
    W3 w = wigner3j_c(1, 1, 2);
    double s5 = csqrt_(5.0);
    for (int t = 0; t < 45; t++) P.c5[t] = (float)(w.w[t] * s5);
    return P;
}

constexpr CGTab CGH = build_cg_c();

template <int I> struct CGC { static constexpr float v = CGH.cg[I]; };
template <int I> struct C5C { static constexpr float v = CGH.c5[I]; };

// ----------------------------------------------------------------------------
// Index-sequence machinery
// ----------------------------------------------------------------------------
template <int... Is> struct iseq {};
template <int N, int... Is> struct mkseq_ : mkseq_<N - 1, N - 1, Is...> {};
template <int... Is> struct mkseq_<0, Is...> { using type = iseq<Is...>; };
template <int N> using mkseq = typename mkseq_<N>::type;

template <int IDX>
__device__ __forceinline__ float cgfma(float x, float s) {
    constexpr float c = CGC<IDX>::v;
    if constexpr (c == 0.0f) return s;
    else return fmaf(c, x, s);            // FFMA-imm form, rt=1
}
template <int IDX>
__device__ __forceinline__ float c5fma(float x, float s) {
    constexpr float c = C5C<IDX>::v;
    if constexpr (c == 0.0f) return s;
    else return fmaf(c, x, s);
}

template <int CGOFF, int R, int RIDX, int... ABs>
__device__ __forceinline__ void cg_step(float xv, float* __restrict__ Hz, iseq<ABs...>) {
    ((Hz[ABs] = cgfma<CGOFF + ABs * R + RIDX>(xv, Hz[ABs])), ...);
}
template <int CGOFF, int R, int... Rs>
__device__ __forceinline__ void cg_stream(const float* __restrict__ x,
                                          float* __restrict__ Hz, iseq<Rs...>) {
    ((cg_step<CGOFF, R, Rs>(x[Rs], Hz, mkseq<R>{})), ...);
}

// ----------------------------------------------------------------------------
// Pair transform on a register buffer.
// ----------------------------------------------------------------------------
template <int L1, int L2, int NCH, int CGOFF>
__device__ __forceinline__ void do_pair(float* __restrict__ x,
                                        const float* __restrict__ Dl,
                                        const float* __restrict__ Dr) {
    constexpr int R = L1 * L2;
#pragma unroll
    for (int q = 0; q < NCH; ++q) {
        float Hz[R];
#pragma unroll
        for (int ab = 0; ab < R; ++ab) Hz[ab] = 0.f;
        cg_stream<CGOFF, R>(x + q * R, Hz, mkseq<R>{});
#pragma unroll
        for (int l = 0; l < L1; ++l) {
            float T[L2];
#pragma unroll
            for (int b = 0; b < L2; ++b) {
                if constexpr (L1 == 1) {
                    T[b] = Hz[b];
                } else {
                    float s = 0.f;
#pragma unroll
                    for (int m = 0; m < L1; ++m)
                        s = fmaf(Dl[l * L1 + m], Hz[m * L2 + b], s);
                    T[b] = s;
                }
            }
#pragma unroll
            for (int k = 0; k < L2; ++k) {
                if constexpr (L2 == 1) {
                    x[q * R + l * L2 + k] = T[0];
                } else {
                    float s = 0.f;
#pragma unroll
                    for (int o = 0; o < L2; ++o)
                        s = fmaf(T[o], Dr[k * L2 + o], s);
                    x[q * R + l * L2 + k] = s;
                }
            }
        }
    }
}

// ----------------------------------------------------------------------------
// D builders (C5 coefficients as immediates).
// ----------------------------------------------------------------------------
template <int N, int N1>
__device__ __forceinline__ float u_ent(const float* __restrict__ d1row) {
    float s = 0.f;
    s = c5fma<(N1 * 3 + 0) * 5 + N>(d1row[0], s);
    s = c5fma<(N1 * 3 + 1) * 5 + N>(d1row[1], s);
    s = c5fma<(N1 * 3 + 2) * 5 + N>(d1row[2], s);
    return s;
}
template <int M, int... MMs>
__device__ __forceinline__ float d2_ent(const float* __restrict__ E, iseq<MMs...>) {
    float s = 0.f;
    ((s = c5fma<MMs * 5 + M>(E[MMs], s)), ...);
    return s;
}
template <int N>
__device__ __forceinline__ void d2_col(const float* __restrict__ D1m, float* __restrict__ D2m) {
    float U[9];
#pragma unroll
    for (int m2 = 0; m2 < 3; ++m2) {
        U[m2 * 3 + 0] = u_ent<N, 0>(D1m + m2 * 3);
        U[m2 * 3 + 1] = u_ent<N, 1>(D1m + m2 * 3);
        U[m2 * 3 + 2] = u_ent<N, 2>(D1m + m2 * 3);
    }
    float E[9];
#pragma unroll
    for (int m1 = 0; m1 < 3; ++m1)
#pragma unroll
        for (int m2 = 0; m2 < 3; ++m2) {
            float s = 0.f;
#pragma unroll
            for (int n1 = 0; n1 < 3; ++n1)
                s = fmaf(D1m[m1 * 3 + n1], U[m2 * 3 + n1], s);
            E[m1 * 3 + m2] = s;
        }
    D2m[0 * 5 + N] = d2_ent<0>(E, mkseq<9>{});
    D2m[1 * 5 + N] = d2_ent<1>(E, mkseq<9>{});
    D2m[2 * 5 + N] = d2_ent<2>(E, mkseq<9>{});
    D2m[3 * 5 + N] = d2_ent<3>(E, mkseq<9>{});
    D2m[4 * 5 + N] = d2_ent<4>(E, mkseq<9>{});
}

// ----------------------------------------------------------------------------
// Float4 streaming row I/O on SMEM with carry registers (OFF local to phase).
// ----------------------------------------------------------------------------
template <int OFF, int SIZE>
__device__ __forceinline__ void load_x(const float4* __restrict__ g, float4& ic,
                                       float* __restrict__ x) {
    constexpr int LO = OFF / 4;
    constexpr int HI = (OFF + SIZE - 1) / 4;
    constexpr int PH = OFF % 4;
#pragma unroll
    for (int f = LO; f <= HI; ++f) {
        float4 v = (f == LO && PH != 0) ? ic : g[f];
        float vv[4] = {v.x, v.y, v.z, v.w};
#pragma unroll
        for (int j = 0; j < 4; ++j) {
            int c = 4 * f + j;
            if (c >= OFF && c < OFF + SIZE) x[c - OFF] = vv[j];
        }
        if (f == HI) ic = v;   // carry boundary f4 to next pair
    }
}

template <int OFF, int SIZE>
__device__ __forceinline__ void store_y(float4* __restrict__ g, float4& oc,
                                        const float* __restrict__ x) {
    constexpr int LO = OFF / 4;
    constexpr int HI = (OFF + SIZE - 1) / 4;
    constexpr int PH = OFF % 4;
    constexpr int PE = (OFF + SIZE) % 4;
#pragma unroll
    for (int f = LO; f <= HI; ++f) {
        float vv[4];
#pragma unroll
        for (int j = 0; j < 4; ++j) {
            int c = 4 * f + j;
            vv[j] = (c >= OFF && c < OFF + SIZE) ? x[c - OFF] : 0.f;
        }
        if (f == LO && PH != 0) {          // merge leading floats from carry
            float ov[4] = {oc.x, oc.y, oc.z, oc.w};
#pragma unroll
            for (int j = 0; j < PH; ++j) vv[j] = ov[j];
        }
        if (f == HI && PE != 0) {
            oc = make_float4(vv[0], vv[1], vv[2], vv[3]);   // hold partial
        } else {
            g[f] = make_float4(vv[0], vv[1], vv[2], vv[3]);
        }
    }
}

// ----------------------------------------------------------------------------
// cp.async helpers
// ----------------------------------------------------------------------------
__device__ __forceinline__ void cp16(void* smem_dst, const void* gsrc) {
    uint32_t sa = (uint32_t)__cvta_generic_to_shared(smem_dst);
    asm volatile("cp.async.cg.shared.global [%0], [%1], 16;" :: "r"(sa), "l"(gsrc));
}
__device__ __forceinline__ void cp_commit() {
    asm volatile("cp.async.commit_group;");
}
template <int N>
__device__ __forceinline__ void cp_wait() {
    asm volatile("cp.async.wait_group %0;" :: "n"(N));
}

// ----------------------------------------------------------------------------
// Kernel: 2 warps per CTA — warp0 computes phase A, warp1 computes phase B
// CONCURRENTLY on the same 32 edges. 8 CTAs/SM = 8 independent pipelines,
// 16 warps/SM. CTA critical path: load -> 1x compute -> 1x store (2x drain).
// ----------------------------------------------------------------------------
__global__ void __launch_bounds__(NTHREADS, 8)
e3_kernel(const float* __restrict__ feat, const float* __restrict__ vec,
          float* __restrict__ out, int n) {
    extern __shared__ float4 sm4[];
    float4* bufA = sm4;                 // EPB x S4
    float4* bufB = sm4 + EPB * S4;      // EPB x S4
    const int tid = threadIdx.x;
    const int warp = tid >> 5;
    const int lane = tid & 31;
    const int e0 = blockIdx.x * EPB;
    const int nvalid = min(EPB, n - e0);

    const float4* g4 = reinterpret_cast<const float4*>(feat);
    float4* o4 = reinterpret_cast<float4*>(out);

    // ---- issue BOTH phase loads (all 64 threads) ----
    const int nA = nvalid * A_F4;
    for (int i = tid; i < nA; i += NTHREADS) {
        int r = i / A_F4, c = i - r * A_F4;
        cp16(&bufA[r * S4 + c], &g4[(size_t)(e0 + r) * 49 + c]);
    }
    const int nB = nvalid * B_F4;
    for (int i = tid; i < nB; i += NTHREADS) {
        int r = i / B_F4, c = i - r * B_F4;
        cp16(&bufB[r * S4 + c], &g4[(size_t)(e0 + r) * 49 + A_F4 + c]);
    }
    cp_commit();

    // ---- each warp builds D1, D2 for its row (overlaps the async loads) ----
    float D1m[9], D2m[25];
    {
        float vx = 0.f, vy = 1.f, vz = 0.f;
        if (lane < nvalid) {
            const int e = e0 + lane;
            vx = vec[3 * e + 0]; vy = vec[3 * e + 1]; vz = vec[3 * e + 2];
        }
        float inv = rsqrtf(fmaf(vx, vx, fmaf(vy, vy, vz * vz)));
        vx *= inv; vy *= inv; vz *= inv;
        float cb = fminf(1.f, fmaxf(-1.f, vy));
        float sb = sqrtf(fmaxf(0.f, 1.f - cb * cb));
        float rho2 = fmaf(vx, vx, vz * vz);
        float ca, sa;
        if (rho2 > 0.f) {
            float ir = rsqrtf(rho2);
            ca = vz * ir; sa = vx * ir;
        } else { ca = 1.f; sa = 0.f; }
        D1m[0] = ca;   D1m[1] = sa * sb; D1m[2] = sa * cb;
        D1m[3] = 0.f;  D1m[4] = cb;      D1m[5] = -sb;
        D1m[6] = -sa;  D1m[7] = ca * sb; D1m[8] = ca * cb;
        d2_col<0>(D1m, D2m);
        d2_col<1>(D1m, D2m);
        d2_col<2>(D1m, D2m);
        d2_col<3>(D1m, D2m);
        d2_col<4>(D1m, D2m);
    }

    // ---- wait for all data, then both warps compute their phase in parallel
    cp_wait<0>();
    __syncthreads();

    if (lane < nvalid) {
        if (warp == 0) {
            float4* row4 = bufA + lane * S4;
            float4 ic = make_float4(0.f, 0.f, 0.f, 0.f);
            float4 oc = ic;
            float x[36];
            load_x<0, 9>(row4, ic, x);   do_pair<1, 1, 9, 0  >(x, D1m, D1m); store_y<0, 9>(row4, oc, x);
            load_x<9, 18>(row4, ic, x);  do_pair<1, 3, 6, 1  >(x, D1m, D1m); store_y<9, 18>(row4, oc, x);
            load_x<27, 15>(row4, ic, x); do_pair<1, 5, 3, 10 >(x, D1m, D2m); store_y<27, 15>(row4, oc, x);
            load_x<42, 18>(row4, ic, x); do_pair<3, 1, 6, 35 >(x, D1m, D1m); store_y<42, 18>(row4, oc, x);
            load_x<60, 36>(row4, ic, x); do_pair<3, 3, 4, 44 >(x, D1m, D1m); store_y<60, 36>(row4, oc, x);
        } else {
            float4* row4 = bufB + lane * S4;
            float4 ic = make_float4(0.f, 0.f, 0.f, 0.f);
            float4 oc = ic;
            float x[36];
            load_x<0, 30>(row4, ic, x);  do_pair<3, 5, 2, 125>(x, D1m, D2m); store_y<0, 30>(row4, oc, x);
            load_x<30, 15>(row4, ic, x); do_pair<5, 1, 3, 350>(x, D2m, D1m); store_y<30, 15>(row4, oc, x);
            load_x<45, 30>(row4, ic, x); do_pair<5, 3, 2, 375>(x, D2m, D1m); store_y<45, 30>(row4, oc, x);
            load_x<75, 25>(row4, ic, x); do_pair<5, 5, 1, 600>(x, D2m, D2m); store_y<75, 25>(row4, oc, x);
        }
    }
    __syncthreads();

    // ---- cooperative store of both buffers (64 threads) ----
    for (int i = tid; i < nA; i += NTHREADS) {
        int r = i / A_F4, c = i - r * A_F4;
        o4[(size_t)(e0 + r) * 49 + c] = bufA[r * S4 + c];
    }
    for (int i = tid; i < nB; i += NTHREADS) {
        int r = i / B_F4, c = i - r * B_F4;
        o4[(size_t)(e0 + r) * 49 + A_F4 + c] = bufB[r * S4 + c];
    }
}

// ----------------------------------------------------------------------------
// Launch
// ----------------------------------------------------------------------------
extern "C" void kernel_launch(void* const* d_in, const int* in_sizes, int n_in,
                              void* d_out, int out_size) {
    (void)n_in; (void)out_size;
    const float* feat = (const float*)d_in[0];
    const float* vec  = (const float*)d_in[1];
    float* out = (float*)d_out;
    const int n = in_sizes[0] / NF;

    cudaFuncSetAttribute(e3_kernel, cudaFuncAttributeMaxDynamicSharedMemorySize, SMEM_BYTES);
    int blocks = (n + EPB - 1) / EPB;
    e3_kernel<<<blocks, NTHREADS, SMEM_BYTES>>>(feat, vec, out, n);
}

// round 17
// speedup vs baseline: 1.2232x; 1.0134x over previous
#include <cuda_runtime.h>
#include <cuda_bf16.h>
#include <cstdint>

// ----------------------------------------------------------------------------
// Constants
// ----------------------------------------------------------------------------
#define NF       196
#define EPB      32
#define NTHREADS 64          // warp0 owns phase A end-to-end, warp1 owns phase B
#define S4       25          // float4 stride per smem row (400B: conflict-free f4 access)
#define A_F4     24          // phase A: cols [0,96)   -> f4 0..23
#define B_F4     25          // phase B: cols [96,196) -> f4 24..48
#define SMEM_BYTES (2 * EPB * S4 * 16)

// pairs (offset,size): ss 0,9  sp 9,18  sd 27,15  ps 42,18  pp 60,36
//                      pd 96,30  ds 126,15  dp 141,30  dd 171,25
// cg offsets: ss0 sp1 sd10 ps35 pp44 pd125 ds350 dp375 dd600

// ----------------------------------------------------------------------------
// Compile-time CG computation: constexpr float64 mirror of the numpy reference.
// ----------------------------------------------------------------------------
struct CD { double re, im; };
constexpr CD cadd(CD a, CD b) { return {a.re + b.re, a.im + b.im}; }
constexpr CD cmulc(CD a, CD b) { return {a.re * b.re - a.im * b.im, a.re * b.im + a.im * b.re}; }
constexpr CD cscale(CD a, double s) { return {a.re * s, a.im * s}; }
constexpr CD cconj(CD a) { return {a.re, -a.im}; }
constexpr bool ciszero(CD a) { return a.re == 0.0 && a.im == 0.0; }

constexpr double cfact(int n) { double r = 1.0; for (int i = 2; i <= n; i++) r *= i; return r; }

constexpr double csqrt_(double x) {
    if (x <= 0.0) return 0.0;
    double y = x > 1.0 ? x : 1.0;
    for (int i = 0; i < 80; i++) {
        double ny = 0.5 * (y + x / y);
        if (ny == y) break;
        y = ny;
    }
    return y;
}

constexpr double su2_cg_c(int j1, int j2, int j3, int m1, int m2, int m3) {
    if (m3 != m1 + m2) return 0.0;
    int vmin = -j1 + j2 + m3;
    if (-j1 + m1 > vmin) vmin = -j1 + m1;
    if (0 > vmin) vmin = 0;
    int vmax = j2 + j3 + m1;
    if (j3 - j1 + j2 < vmax) vmax = j3 - j1 + j2;
    if (j3 + m3 < vmax) vmax = j3 + m3;
    double C = csqrt_((2.0 * j3 + 1.0) * cfact(j3 + j1 - j2) * cfact(j3 - j1 + j2)
                      * cfact(j1 + j2 - j3) * cfact(j3 + m3) * cfact(j3 - m3)
                      / (cfact(j1 + j2 + j3 + 1) * cfact(j1 - m1) * cfact(j1 + m1)
                         * cfact(j2 - m2) * cfact(j2 + m2)));
    double S = 0.0;
    for (int v = vmin; v <= vmax; v++) {
        double sg = ((v + j2 + m2) & 1) ? -1.0 : 1.0;
        S += sg * cfact(j2 + j3 + m1 - v) * cfact(j1 - m1 + v)
             / (cfact(v) * cfact(j3 - j1 + j2 - v) * cfact(j3 + m3 - v)
                * cfact(v + j1 - j2 - m3));
    }
    return C * S;
}

struct QM { CD q[81]; };

constexpr QM change_basis_c(int l) {
    QM Q{};
    int L = 2 * l + 1;
    for (int i = 0; i < L * L; i++) Q.q[i] = CD{0, 0};
    double is2 = 1.0 / csqrt_(2.0);
    for (int m = -l; m < 0; m++) {
        Q.q[(l + m) * L + (l - m)] = CD{is2, 0};
        Q.q[(l + m) * L + (l + m)] = CD{0, -is2};
    }
    Q.q[l * L + l] = CD{1, 0};
    for (int m = 1; m <= l; m++) {
        double sg = (m & 1) ? -1.0 : 1.0;
        Q.q[(l + m) * L + (l + m)] = CD{sg * is2, 0};
        Q.q[(l + m) * L + (l - m)] = CD{0, sg * is2};
    }
    CD ph{1, 0};
    for (int k = 0; k < l; k++) ph = cmulc(ph, CD{0, -1});   // (-i)^l
    for (int i = 0; i < L * L; i++) Q.q[i] = cmulc(Q.q[i], ph);
    return Q;
}

struct W3 { double w[225]; };

constexpr W3 wigner3j_c(int l1, int l2, int l3) {
    int L1 = 2 * l1 + 1, L2 = 2 * l2 + 1, L3 = 2 * l3 + 1;
    QM Q1 = change_basis_c(l1), Q2 = change_basis_c(l2), Q3 = change_basis_c(l3);
    CD acc[225]{};
    for (int t = 0; t < 225; t++) acc[t] = CD{0, 0};
    for (int i = 0; i < L1; i++)
        for (int k = 0; k < L2; k++)
            for (int n = 0; n < L3; n++) {
                double c = su2_cg_c(l1, l2, l3, i - l1, k - l2, n - l3);
                if (c == 0.0) continue;
                for (int j = 0; j < L1; j++) {
                    CD q1 = Q1.q[i * L1 + j];
                    if (ciszero(q1)) continue;
                    for (int l = 0; l < L2; l++) {
                        CD q2 = Q2.q[k * L2 + l];
                        if (ciszero(q2)) continue;
                        CD q12 = cmulc(q1, q2);
                        for (int m = 0; m < L3; m++) {
                            CD q3 = Q3.q[n * L3 + m];
                            if (ciszero(q3)) continue;
                            CD t = cmulc(q12, cconj(q3));
                            int o = (j * L2 + l) * L3 + m;
                            acc[o] = cadd(acc[o], cscale(t, c));
                        }
                    }
                }
            }
    W3 out{};
    double nrm = 0.0;
    for (int t = 0; t < L1 * L2 * L3; t++) { out.w[t] = acc[t].re; nrm += out.w[t] * out.w[t]; }
    nrm = csqrt_(nrm);
    for (int t = 0; t < L1 * L2 * L3; t++) out.w[t] /= nrm;
    return out;
}

struct CGTab { float cg[1225]; float c5[45]; };

constexpr CGTab build_cg_c() {
    CGTab P{};
    const int l1s[9]   = {0, 0, 0, 1, 1, 1, 2, 2, 2};
    const int l2s[9]   = {0, 1, 2, 0, 1, 2, 0, 1, 2};
    const int cgoff[9] = {0, 1, 10, 35, 44, 125, 350, 375, 600};
    for (int p = 0; p < 9; p++) {
        int l1 = l1s[p], l2 = l2s[p];
        int L1 = 2 * l1 + 1, L2 = 2 * l2 + 1, R = L1 * L2;
        int lmin = (l1 > l2) ? (l1 - l2) : (l2 - l1);
        int rof = 0;
        for (int l3 = lmin; l3 <= l1 + l2; l3++) {
            W3 w = wigner3j_c(l1, l2, l3);
            int L3 = 2 * l3 + 1;
            double sc = csqrt_(2.0 * l3 + 1.0);
            for (int a = 0; a < L1; a++)
                for (int b = 0; b < L2; b++)
                    for (int nn = 0; nn < L3; nn++)
                        P.cg[cgoff[p] + (a * L2 + b) * R + rof + nn] =
                            (float)(w.w[(a * L2 + b) * L3 + nn] * sc);
            rof += L3;
        }
    }
    W3 w = wigner3j_c(1, 1, 2);
    double s5 = csqrt_(5.0);
    for (int t = 0; t < 45; t++) P.c5[t] = (float)(w.w[t] * s5);
    return P;
}

constexpr CGTab CGH = build_cg_c();

template <int I> struct CGC { static constexpr float v = CGH.cg[I]; };
template <int I> struct C5C { static constexpr float v = CGH.c5[I]; };

// ----------------------------------------------------------------------------
// Index-sequence machinery
// ----------------------------------------------------------------------------
template <int... Is> struct iseq {};
template <int N, int... Is> struct mkseq_ : mkseq_<N - 1, N - 1, Is...> {};
template <int... Is> struct mkseq_<0, Is...> { using type = iseq<Is...>; };
template <int N> using mkseq = typename mkseq_<N>::type;

template <int IDX>
__device__ __forceinline__ float cgfma(float x, float s) {
    constexpr float c = CGC<IDX>::v;
    if constexpr (c == 0.0f) return s;
    else return fmaf(c, x, s);            // FFMA-imm form, rt=1
}
template <int IDX>
__device__ __forceinline__ float c5fma(float x, float s) {
    constexpr float c = C5C<IDX>::v;
    if constexpr (c == 0.0f) return s;
    else return fmaf(c, x, s);
}

template <int CGOFF, int R, int RIDX, int... ABs>
__device__ __forceinline__ void cg_step(float xv, float* __restrict__ Hz, iseq<ABs...>) {
    ((Hz[ABs] = cgfma<CGOFF + ABs * R + RIDX>(xv, Hz[ABs])), ...);
}
template <int CGOFF, int R, int... Rs>
__device__ __forceinline__ void cg_stream(const float* __restrict__ x,
                                          float* __restrict__ Hz, iseq<Rs...>) {
    ((cg_step<CGOFF, R, Rs>(x[Rs], Hz, mkseq<R>{})), ...);
}

// ----------------------------------------------------------------------------
// Pair transform on a register buffer.
// ----------------------------------------------------------------------------
template <int L1, int L2, int NCH, int CGOFF>
__device__ __forceinline__ void do_pair(float* __restrict__ x,
                                        const float* __restrict__ Dl,
                                        const float* __restrict__ Dr) {
    constexpr int R = L1 * L2;
#pragma unroll
    for (int q = 0; q < NCH; ++q) {
        float Hz[R];
#pragma unroll
        for (int ab = 0; ab < R; ++ab) Hz[ab] = 0.f;
        cg_stream<CGOFF, R>(x + q * R, Hz, mkseq<R>{});
#pragma unroll
        for (int l = 0; l < L1; ++l) {
            float T[L2];
#pragma unroll
            for (int b = 0; b < L2; ++b) {
                if constexpr (L1 == 1) {
                    T[b] = Hz[b];
                } else {
                    float s = 0.f;
#pragma unroll
                    for (int m = 0; m < L1; ++m)
                        s = fmaf(Dl[l * L1 + m], Hz[m * L2 + b], s);
                    T[b] = s;
                }
            }
#pragma unroll
            for (int k = 0; k < L2; ++k) {
                if constexpr (L2 == 1) {
                    x[q * R + l * L2 + k] = T[0];
                } else {
                    float s = 0.f;
#pragma unroll
                    for (int o = 0; o < L2; ++o)
                        s = fmaf(T[o], Dr[k * L2 + o], s);
                    x[q * R + l * L2 + k] = s;
                }
            }
        }
    }
}

// ----------------------------------------------------------------------------
// D builders (C5 coefficients as immediates).
// ----------------------------------------------------------------------------
template <int N, int N1>
__device__ __forceinline__ float u_ent(const float* __restrict__ d1row) {
    float s = 0.f;
    s = c5fma<(N1 * 3 + 0) * 5 + N>(d1row[0], s);
    s = c5fma<(N1 * 3 + 1) * 5 + N>(d1row[1], s);
    s = c5fma<(N1 * 3 + 2) * 5 + N>(d1row[2], s);
    return s;
}
template <int M, int... MMs>
__device__ __forceinline__ float d2_ent(const float* __restrict__ E, iseq<MMs...>) {
    float s = 0.f;
    ((s = c5fma<MMs * 5 + M>(E[MMs], s)), ...);
    return s;
}
template <int N>
__device__ __forceinline__ void d2_col(const float* __restrict__ D1m, float* __restrict__ D2m) {
    float U[9];
#pragma unroll
    for (int m2 = 0; m2 < 3; ++m2) {
        U[m2 * 3 + 0] = u_ent<N, 0>(D1m + m2 * 3);
        U[m2 * 3 + 1] = u_ent<N, 1>(D1m + m2 * 3);
        U[m2 * 3 + 2] = u_ent<N, 2>(D1m + m2 * 3);
    }
    float E[9];
#pragma unroll
    for (int m1 = 0; m1 < 3; ++m1)
#pragma unroll
        for (int m2 = 0; m2 < 3; ++m2) {
            float s = 0.f;
#pragma unroll
            for (int n1 = 0; n1 < 3; ++n1)
                s = fmaf(D1m[m1 * 3 + n1], U[m2 * 3 + n1], s);
            E[m1 * 3 + m2] = s;
        }
    D2m[0 * 5 + N] = d2_ent<0>(E, mkseq<9>{});
    D2m[1 * 5 + N] = d2_ent<1>(E, mkseq<9>{});
    D2m[2 * 5 + N] = d2_ent<2>(E, mkseq<9>{});
    D2m[3 * 5 + N] = d2_ent<3>(E, mkseq<9>{});
    D2m[4 * 5 + N] = d2_ent<4>(E, mkseq<9>{});
}

// ----------------------------------------------------------------------------
// Float4 streaming row I/O on SMEM with carry registers (OFF local to phase).
// ----------------------------------------------------------------------------
template <int OFF, int SIZE>
__device__ __forceinline__ void load_x(const float4* __restrict__ g, float4& ic,
                                       float* __restrict__ x) {
    constexpr int LO = OFF / 4;
    constexpr int HI = (OFF + SIZE - 1) / 4;
    constexpr int PH = OFF % 4;
#pragma unroll
    for (int f = LO; f <= HI; ++f) {
        float4 v = (f == LO && PH != 0) ? ic : g[f];
        float vv[4] = {v.x, v.y, v.z, v.w};
#pragma unroll
        for (int j = 0; j < 4; ++j) {
            int c = 4 * f + j;
            if (c >= OFF && c < OFF + SIZE) x[c - OFF] = vv[j];
        }
        if (f == HI) ic = v;   // carry boundary f4 to next pair
    }
}

template <int OFF, int SIZE>
__device__ __forceinline__ void store_y(float4* __restrict__ g, float4& oc,
                                        const float* __restrict__ x) {
    constexpr int LO = OFF / 4;
    constexpr int HI = (OFF + SIZE - 1) / 4;
    constexpr int PH = OFF % 4;
    constexpr int PE = (OFF + SIZE) % 4;
#pragma unroll
    for (int f = LO; f <= HI; ++f) {
        float vv[4];
#pragma unroll
        for (int j = 0; j < 4; ++j) {
            int c = 4 * f + j;
            vv[j] = (c >= OFF && c < OFF + SIZE) ? x[c - OFF] : 0.f;
        }
        if (f == LO && PH != 0) {          // merge leading floats from carry
            float ov[4] = {oc.x, oc.y, oc.z, oc.w};
#pragma unroll
            for (int j = 0; j < PH; ++j) vv[j] = ov[j];
        }
        if (f == HI && PE != 0) {
            oc = make_float4(vv[0], vv[1], vv[2], vv[3]);   // hold partial
        } else {
            g[f] = make_float4(vv[0], vv[1], vv[2], vv[3]);
        }
    }
}

// ----------------------------------------------------------------------------
// cp.async helpers
// ----------------------------------------------------------------------------
__device__ __forceinline__ void cp16(void* smem_dst, const void* gsrc) {
    uint32_t sa = (uint32_t)__cvta_generic_to_shared(smem_dst);
    asm volatile("cp.async.cg.shared.global [%0], [%1], 16;" :: "r"(sa), "l"(gsrc));
}
__device__ __forceinline__ void cp_commit() {
    asm volatile("cp.async.commit_group;");
}
template <int N>
__device__ __forceinline__ void cp_wait() {
    asm volatile("cp.async.wait_group %0;" :: "n"(N));
}

// ----------------------------------------------------------------------------
// Kernel: WARP-PRIVATE pipelines. Warp0 owns bufA (load+compute+store for
// cols [0,96)), warp1 owns bufB (cols [96,196)). No __syncthreads at all:
// each warp's cp.asyncs are written and read only by its own lanes, so
// wait_group + __syncwarp is sufficient. 8 CTAs/SM = 16 independent
// warp-pipelines per SM.
// ----------------------------------------------------------------------------
__global__ void __launch_bounds__(NTHREADS, 8)
e3_kernel(const float* __restrict__ feat, const float* __restrict__ vec,
          float* __restrict__ out, int n) {
    extern __shared__ float4 sm4[];
    float4* bufA = sm4;                 // EPB x S4 (warp0 private)
    float4* bufB = sm4 + EPB * S4;      // EPB x S4 (warp1 private)
    const int tid = threadIdx.x;
    const int warp = tid >> 5;
    const int lane = tid & 31;
    const int e0 = blockIdx.x * EPB;
    const int nvalid = min(EPB, n - e0);

    const float4* g4 = reinterpret_cast<const float4*>(feat);
    float4* o4 = reinterpret_cast<float4*>(out);

    // ---- each warp issues ONLY its own buffer's loads ----
    if (warp == 0) {
        const int nA = nvalid * A_F4;
        for (int i = lane; i < nA; i += 32) {
            int r = i / A_F4, c = i - r * A_F4;
            cp16(&bufA[r * S4 + c], &g4[(size_t)(e0 + r) * 49 + c]);
        }
    } else {
        const int nB = nvalid * B_F4;
        for (int i = lane; i < nB; i += 32) {
            int r = i / B_F4, c = i - r * B_F4;
            cp16(&bufB[r * S4 + c], &g4[(size_t)(e0 + r) * 49 + A_F4 + c]);
        }
    }
    cp_commit();

    // ---- each warp builds D1, D2 for its row (overlaps the async loads) ----
    float D1m[9], D2m[25];
    {
        float vx = 0.f, vy = 1.f, vz = 0.f;
        if (lane < nvalid) {
            const int e = e0 + lane;
            vx = vec[3 * e + 0]; vy = vec[3 * e + 1]; vz = vec[3 * e + 2];
        }
        float inv = rsqrtf(fmaf(vx, vx, fmaf(vy, vy, vz * vz)));
        vx *= inv; vy *= inv; vz *= inv;
        float cb = fminf(1.f, fmaxf(-1.f, vy));
        float sb = sqrtf(fmaxf(0.f, 1.f - cb * cb));
        float rho2 = fmaf(vx, vx, vz * vz);
        float ca, sa;
        if (rho2 > 0.f) {
            float ir = rsqrtf(rho2);
            ca = vz * ir; sa = vx * ir;
        } else { ca = 1.f; sa = 0.f; }
        D1m[0] = ca;   D1m[1] = sa * sb; D1m[2] = sa * cb;
        D1m[3] = 0.f;  D1m[4] = cb;      D1m[5] = -sb;
        D1m[6] = -sa;  D1m[7] = ca * sb; D1m[8] = ca * cb;
        d2_col<0>(D1m, D2m);
        d2_col<1>(D1m, D2m);
        d2_col<2>(D1m, D2m);
        d2_col<3>(D1m, D2m);
        d2_col<4>(D1m, D2m);
    }

    // ---- wait for OWN loads, compute, store — fully warp-local ----
    cp_wait<0>();
    __syncwarp();

    if (warp == 0) {
        if (lane < nvalid) {
            float4* row4 = bufA + lane * S4;
            float4 ic = make_float4(0.f, 0.f, 0.f, 0.f);
            float4 oc = ic;
            float x[36];
            load_x<0, 9>(row4, ic, x);   do_pair<1, 1, 9, 0  >(x, D1m, D1m); store_y<0, 9>(row4, oc, x);
            load_x<9, 18>(row4, ic, x);  do_pair<1, 3, 6, 1  >(x, D1m, D1m); store_y<9, 18>(row4, oc, x);
            load_x<27, 15>(row4, ic, x); do_pair<1, 5, 3, 10 >(x, D1m, D2m); store_y<27, 15>(row4, oc, x);
            load_x<42, 18>(row4, ic, x); do_pair<3, 1, 6, 35 >(x, D1m, D1m); store_y<42, 18>(row4, oc, x);
            load_x<60, 36>(row4, ic, x); do_pair<3, 3, 4, 44 >(x, D1m, D1m); store_y<60, 36>(row4, oc, x);
        }
        __syncwarp();
        const int nA = nvalid * A_F4;
        for (int i = lane; i < nA; i += 32) {
            int r = i / A_F4, c = i - r * A_F4;
            o4[(size_t)(e0 + r) * 49 + c] = bufA[r * S4 + c];
        }
    } else {
        if (lane < nvalid) {
            float4* row4 = bufB + lane * S4;
            float4 ic = make_float4(0.f, 0.f, 0.f, 0.f);
            float4 oc = ic;
            float x[36];
            load_x<0, 30>(row4, ic, x);  do_pair<3, 5, 2, 125>(x, D1m, D2m); store_y<0, 30>(row4, oc, x);
            load_x<30, 15>(row4, ic, x); do_pair<5, 1, 3, 350>(x, D2m, D1m); store_y<30, 15>(row4, oc, x);
            load_x<45, 30>(row4, ic, x); do_pair<5, 3, 2, 375>(x, D2m, D1m); store_y<45, 30>(row4, oc, x);
            load_x<75, 25>(row4, ic, x); do_pair<5, 5, 1, 600>(x, D2m, D2m); store_y<75, 25>(row4, oc, x);
        }
        __syncwarp();
        const int nB = nvalid * B_F4;
        for (int i = lane; i < nB; i += 32) {
            int r = i / B_F4, c = i - r * B_F4;
            o4[(size_t)(e0 + r) * 49 + A_F4 + c] = bufB[r * S4 + c];
        }
    }
}

// ----------------------------------------------------------------------------
// Launch
// ----------------------------------------------------------------------------
extern "C" void kernel_launch(void* const* d_in, const int* in_sizes, int n_in,
                              void* d_out, int out_size) {
    (void)n_in; (void)out_size;
    const float* feat = (const float*)d_in[0];
    const float* vec  = (const float*)d_in[1];
    float* out = (float*)d_out;
    const int n = in_sizes[0] / NF;

    cudaFuncSetAttribute(e3_kernel, cudaFuncAttributeMaxDynamicSharedMemorySize, SMEM_BYTES);
    int blocks = (n + EPB - 1) / EPB;
    e3_kernel<<<blocks, NTHREADS, SMEM_BYTES>>>(feat, vec, out, n);
}